// round 1
// baseline (speedup 1.0000x reference)
#include <cuda_runtime.h>
#include <cstdint>
#include <cstddef>

// ---------------------------------------------------------------------------
// Spiking conv + winner-takes-all, fused.
//   potentials[b,o,ox,oy,t] = sum over input spikes (i,kx,ky,s) in the 3x3
//   stride-2 window of resp[o,(i,kx,ky)][t-s-1], resp = StepFireLeak kernel.
//   Then per (b,ox,oy): sequential WTA over t with 48-step refractory.
// One CTA per (b, ox, oy). warp = 19-wide time chunk, lane = output channel.
// ---------------------------------------------------------------------------

#define COUT   32
#define W18    18          // C_IN * 3 * 3
#define KS     48
#define TIN    100
#define TOUT   149
#define NSPAT  31
#define THETA  5.4f

// resp table, layout [w18][tau][o]  (o innermost -> coalesced lane loads)
__device__ float g_resp[W18 * KS * COUT];

__global__ void resp_precompute(const float* __restrict__ weight) {
    int idx = blockIdx.x * blockDim.x + threadIdx.x;
    if (idx >= W18 * KS * COUT) return;
    int o   = idx & 31;
    int wt  = idx >> 5;          // w*48 + tau
    int tau = wt % KS;
    int w   = wt / KS;
    float wv = weight[o * W18 + w];
    float tf = (float)tau;
    float ts = tf * 0.0625f;                              // t/16
    float tl = -(tf - wv * 16.0f) * 0.03125f + wv;        // -(t-16w)/32 + w
    g_resp[idx] = fmaxf(0.0f, fminf(ts, tl));
}

__global__ __launch_bounds__(256)
void wta_kernel(const float* __restrict__ xin, float* __restrict__ out) {
    __shared__ unsigned      s_bits[72];      // 18 rows x 4 words of spike bits
    __shared__ unsigned short s_spk[1800];    // compacted spike list (w<<7 | s)
    __shared__ int            s_n;
    __shared__ unsigned char  s_cand[152];    // per-t: winner if >THETA else 255
    __shared__ signed char    s_win[152];     // per-t: winner after refractory

    const int tid  = threadIdx.x;
    const int lane = tid & 31;
    const int wp   = tid >> 5;                // 8 warps
    const int bx   = blockIdx.x;              // n = ox*31 + oy
    const int b    = blockIdx.y;
    const int ox   = bx / NSPAT;
    const int oy   = bx - ox * NSPAT;

    // ---- stage 1: build spike bitmasks (72 tasks = 18 rows x 4 words) ----
    float vv[9];
#pragma unroll
    for (int q = 0; q < 9; ++q) {
        int task = wp + q * 8;                // < 72
        int w    = task >> 2;
        int seg  = task & 3;
        int i    = w / 9;
        int rem  = w - i * 9;
        int kx   = rem / 3;
        int ky   = rem - kx * 3;
        int t    = seg * 32 + lane;
        const float* row = xin +
            ((((size_t)b * 2 + i) * 64 + (2 * ox + kx)) * 64 + (2 * oy + ky)) * TIN;
        vv[q] = (t < TIN) ? row[t] : 0.0f;
    }
#pragma unroll
    for (int q = 0; q < 9; ++q) {
        unsigned m = __ballot_sync(0xffffffffu, vv[q] != 0.0f);
        if (lane == 0) s_bits[wp + q * 8] = m;
    }
    __syncthreads();

    // ---- stage 2: deterministic compaction into spike list (warp 0) ----
    if (wp == 0) {
        int cnt = 0;
        for (int base = 0; base < 72; base += 32) {
            int wi = base + lane;
            unsigned m = (wi < 72) ? s_bits[wi] : 0u;
            int c = __popc(m);
            int pre = c;
#pragma unroll
            for (int d = 1; d < 32; d <<= 1) {
                int v = __shfl_up_sync(0xffffffffu, pre, d);
                if (lane >= d) pre += v;
            }
            int off = cnt + pre - c;
            int wrow = wi >> 2;
            int sb   = (wi & 3) << 5;
            while (m) {
                int bp = __ffs(m) - 1;
                m &= m - 1;
                s_spk[off++] = (unsigned short)((wrow << 7) | (sb + bp));
            }
            cnt += __shfl_sync(0xffffffffu, pre, 31);
        }
        if (lane == 0) s_n = cnt;
    }
    __syncthreads();

    // ---- stage 3: accumulate potentials in registers ----
    // warp wp owns t in [t0, t0+18], lane owns channel o = lane
    const int t0 = wp * 19;
    const int o  = lane;
    float acc[19];
#pragma unroll
    for (int j = 0; j < 19; ++j) acc[j] = 0.0f;

    const int n = s_n;
    for (int k = 0; k < n; ++k) {
        int ws = s_spk[k];                    // smem broadcast
        int w  = ws >> 7;
        int s  = ws & 127;
        // spike contributes to t in [s+1, s+48]; skip if no overlap w/ chunk
        if (s > t0 + 17 || s + 48 < t0) continue;
        int base = (w * KS + (t0 - s - 1)) * COUT + o;
#pragma unroll
        for (int j = 0; j < 19; ++j) {
            int tau = t0 + j - s - 1;
            if (tau >= 0 && tau < KS)
                acc[j] += __ldg(&g_resp[base + j * COUT]);
        }
    }

    // ---- stage 4: per-t argmax over channels (warp reduce, ties -> low idx) ----
#pragma unroll
    for (int j = 0; j < 19; ++j) {
        int t = t0 + j;
        if (t < TOUT) {
            float bv = acc[j];
            int   bi = lane;
#pragma unroll
            for (int off = 16; off > 0; off >>= 1) {
                float ovv = __shfl_down_sync(0xffffffffu, bv, off);
                int   oi  = __shfl_down_sync(0xffffffffu, bi, off);
                if (ovv > bv || (ovv == bv && oi < bi)) { bv = ovv; bi = oi; }
            }
            if (lane == 0)
                s_cand[t] = (bv > THETA) ? (unsigned char)bi : (unsigned char)255;
        }
    }
    __syncthreads();

    // ---- stage 5: sequential depression scan ----
    if (tid == 0) {
        int dep = 0;
#pragma unroll 1
        for (int t = 0; t < TOUT; ++t) {
            int c = s_cand[t];
            int winv = -1;
            if (dep == 0 && c != 255) { winv = c; dep = 48; }  // 48-1 below -> 47
            s_win[t] = (signed char)winv;
            dep = dep > 0 ? dep - 1 : 0;
        }
    }
    __syncthreads();

    // ---- stage 6: write output rows (coalesced, every element written) ----
#pragma unroll
    for (int r = 0; r < 4; ++r) {
        int oc = wp * 4 + r;
        float* orow = out + (((size_t)b * COUT + oc) * (NSPAT * NSPAT) + bx) * TOUT;
        for (int t = lane; t < TOUT; t += 32)
            orow[t] = ((int)s_win[t] == oc) ? 1.0f : 0.0f;
    }
}

extern "C" void kernel_launch(void* const* d_in, const int* in_sizes, int n_in,
                              void* d_out, int out_size) {
    const float* spikes = (const float*)d_in[0];
    const float* weight = (const float*)d_in[1];
    // defensive: identify weight by its element count (32*2*3*3 = 576)
    if (n_in >= 2 && in_sizes[0] == 576) {
        spikes = (const float*)d_in[1];
        weight = (const float*)d_in[0];
    }

    resp_precompute<<<(W18 * KS * COUT + 255) / 256, 256>>>(weight);

    dim3 grid(NSPAT * NSPAT, 16);   // (n, batch)
    wta_kernel<<<grid, 256>>>(spikes, (float*)d_out);
}

// round 2
// speedup vs baseline: 1.7240x; 1.7240x over previous
#include <cuda_runtime.h>
#include <cstdint>
#include <cstddef>

// ---------------------------------------------------------------------------
// Spiking conv + winner-takes-all, fused. Round 2: vectorized table gather.
//   One CTA per (b, ox, oy). 8 warps, each owns a 20-wide t-chunk.
//   Lane = jj*8+oq: jj = tau sub-phase (4 taus per LDG.128), oq = 4-channel grp.
// ---------------------------------------------------------------------------

#define COUT   32
#define W18    18          // C_IN * 3 * 3
#define KS     48
#define TIN    100
#define TOUT   149
#define NSPAT  31
#define THETA  5.4f
#define CHUNK  20

// resp table, layout [w18][tau][o]  (o innermost -> coalesced lane loads)
__device__ float g_resp[W18 * KS * COUT];

__global__ void resp_precompute(const float* __restrict__ weight) {
    int idx = blockIdx.x * blockDim.x + threadIdx.x;
    if (idx >= W18 * KS * COUT) return;
    int o   = idx & 31;
    int wt  = idx >> 5;          // w*48 + tau
    int tau = wt % KS;
    int w   = wt / KS;
    float wv = weight[o * W18 + w];
    float tf = (float)tau;
    float ts = tf * 0.0625f;                              // t/16
    float tl = -(tf - wv * 16.0f) * 0.03125f + wv;        // -(t-16w)/32 + w
    g_resp[idx] = fmaxf(0.0f, fminf(ts, tl));
}

__global__ __launch_bounds__(256)
void wta_kernel(const float* __restrict__ xin, float* __restrict__ out) {
    __shared__ unsigned      s_bits[72];      // 18 rows x 4 words of spike bits
    __shared__ int4          s_spk4[456];     // 1824 packed spike entries
    __shared__ int           s_n;
    __shared__ unsigned char s_cand[160];     // per-t: winner if >THETA else 255
    __shared__ signed char   s_win[160];      // per-t: winner after refractory

    int* s_spk = (int*)s_spk4;

    const int tid  = threadIdx.x;
    const int lane = tid & 31;
    const int wp   = tid >> 5;                // 8 warps
    const int bx   = blockIdx.x;              // n = ox*31 + oy
    const int b    = blockIdx.y;
    const int ox   = bx / NSPAT;
    const int oy   = bx - ox * NSPAT;

    // ---- stage 1: build spike bitmasks (72 tasks = 18 rows x 4 words) ----
    float vv[9];
#pragma unroll
    for (int q = 0; q < 9; ++q) {
        int task = wp + q * 8;                // < 72
        int w    = task >> 2;
        int seg  = task & 3;
        int i    = w / 9;
        int rem  = w - i * 9;
        int kx   = rem / 3;
        int ky   = rem - kx * 3;
        int t    = seg * 32 + lane;
        const float* row = xin +
            ((((size_t)b * 2 + i) * 64 + (2 * ox + kx)) * 64 + (2 * oy + ky)) * TIN;
        vv[q] = (t < TIN) ? row[t] : 0.0f;
    }
#pragma unroll
    for (int q = 0; q < 9; ++q) {
        unsigned m = __ballot_sync(0xffffffffu, vv[q] != 0.0f);
        if (lane == 0) s_bits[wp + q * 8] = m;
    }
    __syncthreads();

    // ---- stage 2: deterministic compaction into spike list (warp 0) ----
    // entry = ((w*48 - s - 1 + 101) << 8) | s   (epart biased to 10 bits)
    if (wp == 0) {
        int cnt = 0;
        for (int base = 0; base < 72; base += 32) {
            int wi = base + lane;
            unsigned m = (wi < 72) ? s_bits[wi] : 0u;
            int c = __popc(m);
            int pre = c;
#pragma unroll
            for (int d = 1; d < 32; d <<= 1) {
                int v = __shfl_up_sync(0xffffffffu, pre, d);
                if (lane >= d) pre += v;
            }
            int off  = cnt + pre - c;
            int wrow = wi >> 2;
            int sb   = (wi & 3) << 5;
            while (m) {
                int bp = __ffs(m) - 1;
                m &= m - 1;
                int s = sb + bp;
                s_spk[off++] = ((wrow * KS - s - 1 + 101) << 8) | s;
            }
            cnt += __shfl_sync(0xffffffffu, pre, 31);
        }
        if (lane == 0) {
            s_n = cnt;
            int cpad = (cnt + 3) & ~3;
            for (int z = cnt; z < cpad; ++z) s_spk[z] = 255;  // s=255 -> skipped
        }
    }
    __syncthreads();

    // ---- stage 3: accumulate potentials (vectorized gather) ----
    const int jj = lane >> 3;                 // tau sub-phase 0..3
    const int oq = lane & 7;                  // channel quad 0..7
    const int t0 = wp * CHUNK;

    float4 acc[5];
#pragma unroll
    for (int k2 = 0; k2 < 5; ++k2) acc[k2] = make_float4(0.f, 0.f, 0.f, 0.f);

    const int nq = (s_n + 3) >> 2;
    const float4* tbl = (const float4*)g_resp + jj * 8 + oq;   // lane base

    for (int k4 = 0; k4 < nq; ++k4) {
        int4 e4 = s_spk4[k4];
        int ee[4] = {e4.x, e4.y, e4.z, e4.w};
#pragma unroll
        for (int q = 0; q < 4; ++q) {
            int e = ee[q];
            int s = e & 255;
            if ((unsigned)(s + KS - t0) <= 66u) {      // overlap with chunk
                int epart = (e >> 8) - 101;            // w*48 - s - 1
                int taub  = t0 - s - 1 + jj;           // tau of slot k2=0
                const float4* p = tbl + (epart + t0) * 8;
#pragma unroll
                for (int k2 = 0; k2 < 5; ++k2) {
                    if ((unsigned)(taub + 4 * k2) < (unsigned)KS) {
                        float4 v = __ldg(p + 32 * k2);
                        acc[k2].x += v.x;
                        acc[k2].y += v.y;
                        acc[k2].z += v.z;
                        acc[k2].w += v.w;
                    }
                }
            }
        }
    }

    // ---- stage 4: per-t argmax (float4 local, then 8-lane group reduce) ----
#pragma unroll
    for (int k2 = 0; k2 < 5; ++k2) {
        int t = t0 + 4 * k2 + jj;
        float bv = acc[k2].x;
        int   bi = oq * 4;
        if (acc[k2].y > bv) { bv = acc[k2].y; bi = oq * 4 + 1; }
        if (acc[k2].z > bv) { bv = acc[k2].z; bi = oq * 4 + 2; }
        if (acc[k2].w > bv) { bv = acc[k2].w; bi = oq * 4 + 3; }
#pragma unroll
        for (int off = 4; off > 0; off >>= 1) {
            float ov = __shfl_down_sync(0xffffffffu, bv, off, 8);
            int   oi = __shfl_down_sync(0xffffffffu, bi, off, 8);
            if (ov > bv) { bv = ov; bi = oi; }   // strict >: lower channel wins ties
        }
        if (oq == 0 && t < TOUT)
            s_cand[t] = (bv > THETA) ? (unsigned char)bi : (unsigned char)255;
    }
    __syncthreads();

    // ---- stage 5: sequential depression scan ----
    if (tid == 0) {
        int dep = 0;
#pragma unroll 1
        for (int t = 0; t < TOUT; ++t) {
            int c = s_cand[t];
            int winv = -1;
            if (dep == 0 && c != 255) { winv = c; dep = KS; }
            s_win[t] = (signed char)winv;
            dep = dep > 0 ? dep - 1 : 0;
        }
    }
    __syncthreads();

    // ---- stage 6: write output rows (coalesced, every element written) ----
#pragma unroll
    for (int r = 0; r < 4; ++r) {
        int oc = wp * 4 + r;
        float* orow = out + (((size_t)b * COUT + oc) * (NSPAT * NSPAT) + bx) * TOUT;
        for (int t = lane; t < TOUT; t += 32)
            orow[t] = ((int)s_win[t] == oc) ? 1.0f : 0.0f;
    }
}

extern "C" void kernel_launch(void* const* d_in, const int* in_sizes, int n_in,
                              void* d_out, int out_size) {
    const float* spikes = (const float*)d_in[0];
    const float* weight = (const float*)d_in[1];
    if (n_in >= 2 && in_sizes[0] == 576) {     // defensive input identification
        spikes = (const float*)d_in[1];
        weight = (const float*)d_in[0];
    }

    resp_precompute<<<(W18 * KS * COUT + 255) / 256, 256>>>(weight);

    dim3 grid(NSPAT * NSPAT, 16);   // (n, batch)
    wta_kernel<<<grid, 256>>>(spikes, (float*)d_out);
}